// round 13
// baseline (speedup 1.0000x reference)
#include <cuda_runtime.h>
#include <cuda_bf16.h>
#include <math.h>

#define NTOT 65536
#define ETOT 1048576
#define INDIM 64
#define HDIM 128
#define NB 128
#define NPG 512
#define KKEEP 410   // ceil(0.8*512)

// ---------------- device scratch (no allocations allowed) ----------------
__device__ float g_h  [(size_t)NTOT * HDIM];
__device__ float g_hn [(size_t)NTOT * HDIM];
__device__ float g_agg[(size_t)NTOT * HDIM];
__device__ int   g_deg   [NTOT];
__device__ int   g_incl  [NTOT];
__device__ int   g_rowptr[NTOT + 1];
__device__ int   g_fill  [NTOT];
__device__ int   g_col   [ETOT];
__device__ int   g_bsum[256];
__device__ int   g_boff[256];
__device__ float g_t    [NTOT];
__device__ float g_score[NTOT];
__device__ float g_scale[NTOT];
__device__ int   g_kept [NTOT];
__device__ int   g_kdeg [NTOT];
__device__ float g_xs   [NB * 4 * HDIM];   // xcat [B][4H]

// bf16 hi/lo transposed weights: 8 slots of [N=128][K<=128]
__device__ unsigned short g_whi[8 * 128 * 128];
__device__ unsigned short g_wlo[8 * 128 * 128];

// ---------------- helpers ----------------
__device__ __forceinline__ float wredf(float v) {
    v += __shfl_xor_sync(0xFFFFFFFFu, v, 16);
    v += __shfl_xor_sync(0xFFFFFFFFu, v, 8);
    v += __shfl_xor_sync(0xFFFFFFFFu, v, 4);
    v += __shfl_xor_sync(0xFFFFFFFFu, v, 2);
    v += __shfl_xor_sync(0xFFFFFFFFu, v, 1);
    return v;
}

// ---------------- CSR build ----------------
__global__ void k_init() {
    int i = blockIdx.x * 256 + threadIdx.x;
    g_deg[i] = 0;
    g_xs[i] = 0.f;
}

__global__ void k_hist(const int* __restrict__ dst) {
    int e = blockIdx.x * 256 + threadIdx.x;
    atomicAdd(&g_deg[dst[e]], 1);
}

__global__ void k_scan1() {
    __shared__ int s[256];
    int i = blockIdx.x * 256 + threadIdx.x;
    int v = g_deg[i];
    s[threadIdx.x] = v;
    __syncthreads();
    for (int off = 1; off < 256; off <<= 1) {
        int t = (threadIdx.x >= off) ? s[threadIdx.x - off] : 0;
        __syncthreads();
        s[threadIdx.x] += t;
        __syncthreads();
    }
    g_incl[i] = s[threadIdx.x];
    if (threadIdx.x == 255) g_bsum[blockIdx.x] = s[255];
}

__global__ void k_scan2() {
    __shared__ int s[256];
    int v = g_bsum[threadIdx.x];
    s[threadIdx.x] = v;
    __syncthreads();
    for (int off = 1; off < 256; off <<= 1) {
        int t = (threadIdx.x >= off) ? s[threadIdx.x - off] : 0;
        __syncthreads();
        s[threadIdx.x] += t;
        __syncthreads();
    }
    g_boff[threadIdx.x] = s[threadIdx.x] - v;
}

__global__ void k_scan3() {
    int i = blockIdx.x * 256 + threadIdx.x;
    int base = g_boff[blockIdx.x];
    int incl = g_incl[i];
    int rp = base + incl - g_deg[i];
    g_rowptr[i] = rp;
    g_fill[i] = rp;
    if (i == NTOT - 1) g_rowptr[NTOT] = base + incl;
}

__global__ void k_scatter(const int* __restrict__ src, const int* __restrict__ dst) {
    int e = blockIdx.x * 256 + threadIdx.x;
    int p = atomicAdd(&g_fill[dst[e]], 1);
    g_col[p] = src[e];
}

// ---------------- weight prep: fp32 [K][128] -> bf16 hi/lo transposed [128][K] ----------------
__global__ void k_prepw(const float* __restrict__ W, int K, int slot, int slotStride) {
    int z = blockIdx.z;
    const float* Ws = W + (size_t)z * K * 128;
    unsigned short* oh = g_whi + (size_t)(slot + z * slotStride) * 16384;
    unsigned short* ol = g_wlo + (size_t)(slot + z * slotStride) * 16384;
    int idx = blockIdx.x * 256 + threadIdx.x;
    if (idx >= K * 128) return;
    int n = idx / K, k = idx % K;
    float v = Ws[(size_t)k * 128 + n];
    __nv_bfloat16 h = __float2bfloat16_rn(v);
    __nv_bfloat16 l = __float2bfloat16_rn(v - __bfloat162float(h));
    oh[idx] = __bfloat16_as_ushort(h);
    ol[idx] = __bfloat16_as_ushort(l);
}

// ---------------- SpMM (mean aggregation), warp per node ----------------
__global__ void k_spmm64(const float* __restrict__ xin, float* __restrict__ outp) {
    int node = (blockIdx.x * blockDim.x + threadIdx.x) >> 5;
    if (node >= NTOT) return;
    int lane = threadIdx.x & 31;
    int s = g_rowptr[node], e = g_rowptr[node + 1];
    float ax = 0.f, ay = 0.f;
    int i = s;
    for (; i + 3 < e; i += 4) {
        int s0 = g_col[i], s1 = g_col[i + 1], s2 = g_col[i + 2], s3 = g_col[i + 3];
        float2 v0 = *((const float2*)(xin + (size_t)s0 * INDIM) + lane);
        float2 v1 = *((const float2*)(xin + (size_t)s1 * INDIM) + lane);
        float2 v2 = *((const float2*)(xin + (size_t)s2 * INDIM) + lane);
        float2 v3 = *((const float2*)(xin + (size_t)s3 * INDIM) + lane);
        ax += v0.x + v1.x + v2.x + v3.x;
        ay += v0.y + v1.y + v2.y + v3.y;
    }
    for (; i < e; i++) {
        int s0 = g_col[i];
        float2 v0 = *((const float2*)(xin + (size_t)s0 * INDIM) + lane);
        ax += v0.x; ay += v0.y;
    }
    int c = g_deg[node];
    float inv = 1.f / (float)(c > 1 ? c : 1);
    *((float2*)(outp + (size_t)node * INDIM) + lane) = make_float2(ax * inv, ay * inv);
}

__global__ void k_spmm128(const float* __restrict__ xin, float* __restrict__ outp,
                          const int* __restrict__ cnt) {
    int node = (blockIdx.x * blockDim.x + threadIdx.x) >> 5;
    if (node >= NTOT) return;
    int lane = threadIdx.x & 31;
    int s = g_rowptr[node], e = g_rowptr[node + 1];
    float ax = 0.f, ay = 0.f, az = 0.f, aw = 0.f;
    int i = s;
    for (; i + 3 < e; i += 4) {
        int s0 = g_col[i], s1 = g_col[i + 1], s2 = g_col[i + 2], s3 = g_col[i + 3];
        float4 v0 = *((const float4*)(xin + (size_t)s0 * HDIM) + lane);
        float4 v1 = *((const float4*)(xin + (size_t)s1 * HDIM) + lane);
        float4 v2 = *((const float4*)(xin + (size_t)s2 * HDIM) + lane);
        float4 v3 = *((const float4*)(xin + (size_t)s3 * HDIM) + lane);
        ax += v0.x + v1.x + v2.x + v3.x;
        ay += v0.y + v1.y + v2.y + v3.y;
        az += v0.z + v1.z + v2.z + v3.z;
        aw += v0.w + v1.w + v2.w + v3.w;
    }
    for (; i < e; i++) {
        int s0 = g_col[i];
        float4 v0 = *((const float4*)(xin + (size_t)s0 * HDIM) + lane);
        ax += v0.x; ay += v0.y; az += v0.z; aw += v0.w;
    }
    int c = cnt[node];
    float inv = 1.f / (float)(c > 1 ? c : 1);
    *((float4*)(outp + (size_t)node * HDIM) + lane) =
        make_float4(ax * inv, ay * inv, az * inv, aw * inv);
}

// SpMM with per-source scale (SAGPool) + inline kept-degree; writes g_kdeg for conv[2].
__global__ void k_spmm128s(const float* __restrict__ xin, float* __restrict__ outp) {
    int node = (blockIdx.x * blockDim.x + threadIdx.x) >> 5;
    if (node >= NTOT) return;
    int lane = threadIdx.x & 31;
    int s = g_rowptr[node], e = g_rowptr[node + 1];
    float ax = 0.f, ay = 0.f, az = 0.f, aw = 0.f;
    int kc = 0;
    int i = s;
    for (; i + 1 < e; i += 2) {
        int s0 = g_col[i], s1 = g_col[i + 1];
        float sc0 = g_scale[s0], sc1 = g_scale[s1];
        kc += g_kept[s0] + g_kept[s1];
        float4 v0 = *((const float4*)(xin + (size_t)s0 * HDIM) + lane);
        float4 v1 = *((const float4*)(xin + (size_t)s1 * HDIM) + lane);
        ax += v0.x * sc0 + v1.x * sc1;
        ay += v0.y * sc0 + v1.y * sc1;
        az += v0.z * sc0 + v1.z * sc1;
        aw += v0.w * sc0 + v1.w * sc1;
    }
    if (i < e) {
        int s0 = g_col[i];
        float sc0 = g_scale[s0];
        kc += g_kept[s0];
        float4 v0 = *((const float4*)(xin + (size_t)s0 * HDIM) + lane);
        ax += v0.x * sc0; ay += v0.y * sc0; az += v0.z * sc0; aw += v0.w * sc0;
    }
    float inv = 1.f / (float)(kc > 1 ? kc : 1);
    *((float4*)(outp + (size_t)node * HDIM) + lane) =
        make_float4(ax * inv, ay * inv, az * inv, aw * inv);
    if (lane == 0) g_kdeg[node] = kc;
}

// ---------------- tensor-core dual GEMM (persistent, fused mean-pool) ----------------
// C = relu(A1@W1 + (scale2 .* A2)@W2 + b) * keptMask; also atomically accumulates
// per-graph column means into g_xs[graph][xslot*128..] (scaled by xinv).

#define AS_STR 24
#define NTILES 512
#define GEMM_GRID 296   // 148 SMs x 2 resident blocks

__device__ __forceinline__ void mma16816(float* d, const unsigned* a, unsigned b0, unsigned b1) {
    asm volatile(
        "mma.sync.aligned.m16n8k16.row.col.f32.bf16.bf16.f32 "
        "{%0,%1,%2,%3}, {%4,%5,%6,%7}, {%8,%9}, {%0,%1,%2,%3};\n"
        : "+f"(d[0]), "+f"(d[1]), "+f"(d[2]), "+f"(d[3])
        : "r"(a[0]), "r"(a[1]), "r"(a[2]), "r"(a[3]), "r"(b0), "r"(b1));
}

__device__ __forceinline__ unsigned pack2(float x, float y, unsigned& lo) {
    __nv_bfloat16 hx = __float2bfloat16_rn(x);
    __nv_bfloat16 hy = __float2bfloat16_rn(y);
    __nv_bfloat16 lx = __float2bfloat16_rn(x - __bfloat162float(hx));
    __nv_bfloat16 ly = __float2bfloat16_rn(y - __bfloat162float(hy));
    lo = (unsigned)__bfloat16_as_ushort(lx) | ((unsigned)__bfloat16_as_ushort(ly) << 16);
    return (unsigned)__bfloat16_as_ushort(hx) | ((unsigned)__bfloat16_as_ushort(hy) << 16);
}

__global__ void __launch_bounds__(256, 2)
k_gemm_tc(const float* __restrict__ A1, int K1, int slot1,
          const float* __restrict__ A2, int K2, int slot2,
          const float* __restrict__ aScale2,
          const float* __restrict__ bias, const int* __restrict__ keptMask,
          float* __restrict__ C, int xslot, float xinv) {
    __shared__ __align__(16) unsigned short As_hi[2][128 * AS_STR];
    __shared__ __align__(16) unsigned short As_lo[2][128 * AS_STR];
    __shared__ __align__(16) unsigned short Bs_hi[2][128 * AS_STR];
    __shared__ __align__(16) unsigned short Bs_lo[2][128 * AS_STR];
    __shared__ float colsum[128];

    const int tid = threadIdx.x, wid = tid >> 5, lane = tid & 31;
    const int wm = (wid & 3) * 32;
    const int wn = (wid >> 2) * 64;
    const int groupID = lane >> 2, tig = lane & 3;

    const int sr = tid >> 1;
    const int sc = (tid & 1) * 8;

    const int NC1 = K1 >> 4;
    const int NC = NC1 + (K2 >> 4);

    for (int tile = blockIdx.x; tile < NTILES; tile += gridDim.x) {
        const int bm = tile * 128;

        float acc[2][8][4];
#pragma unroll
        for (int mt = 0; mt < 2; mt++)
#pragma unroll
            for (int nt = 0; nt < 8; nt++)
#pragma unroll
                for (int j = 0; j < 4; j++) acc[mt][nt][j] = 0.f;

        float4 f0, f1;
        uint4 wh, wl;
        float rowsc;

#define FETCH(cc) do {                                                         \
    int sel = ((cc) >= NC1);                                                   \
    int k0 = (sel ? (cc) - NC1 : (cc)) << 4;                                   \
    const float* A = sel ? A2 : A1;                                            \
    int K = sel ? K2 : K1;                                                     \
    const unsigned short* Wh = g_whi + (size_t)(sel ? slot2 : slot1) * 16384;  \
    const unsigned short* Wl = g_wlo + (size_t)(sel ? slot2 : slot1) * 16384;  \
    const float* ap = A + (size_t)(bm + sr) * K + k0 + sc;                     \
    f0 = *(const float4*)ap;                                                   \
    f1 = *(const float4*)(ap + 4);                                             \
    rowsc = (sel && aScale2) ? aScale2[bm + sr] : 1.f;                         \
    wh = *(const uint4*)(Wh + (size_t)sr * K + k0 + sc);                       \
    wl = *(const uint4*)(Wl + (size_t)sr * K + k0 + sc);                       \
} while (0)

#define STOREBUF(buf) do {                                                     \
    unsigned l0, l1, l2, l3;                                                   \
    unsigned h0 = pack2(f0.x * rowsc, f0.y * rowsc, l0);                       \
    unsigned h1 = pack2(f0.z * rowsc, f0.w * rowsc, l1);                       \
    unsigned h2 = pack2(f1.x * rowsc, f1.y * rowsc, l2);                       \
    unsigned h3 = pack2(f1.z * rowsc, f1.w * rowsc, l3);                       \
    *(uint4*)&As_hi[buf][sr * AS_STR + sc] = make_uint4(h0, h1, h2, h3);       \
    *(uint4*)&As_lo[buf][sr * AS_STR + sc] = make_uint4(l0, l1, l2, l3);       \
    *(uint4*)&Bs_hi[buf][sr * AS_STR + sc] = wh;                               \
    *(uint4*)&Bs_lo[buf][sr * AS_STR + sc] = wl;                               \
} while (0)

        FETCH(0);
        STOREBUF(0);
        __syncthreads();

        for (int c = 0; c < NC; c++) {
            int cur = c & 1;
            if (c + 1 < NC) FETCH(c + 1);

            unsigned ah[2][4], al[2][4];
#pragma unroll
            for (int mt = 0; mt < 2; mt++) {
                int m0 = wm + mt * 16 + groupID;
                const unsigned short* p = &As_hi[cur][m0 * AS_STR + 2 * tig];
                ah[mt][0] = *(const unsigned*)p;
                ah[mt][1] = *(const unsigned*)(p + 8 * AS_STR);
                ah[mt][2] = *(const unsigned*)(p + 8);
                ah[mt][3] = *(const unsigned*)(p + 8 * AS_STR + 8);
                const unsigned short* q = &As_lo[cur][m0 * AS_STR + 2 * tig];
                al[mt][0] = *(const unsigned*)q;
                al[mt][1] = *(const unsigned*)(q + 8 * AS_STR);
                al[mt][2] = *(const unsigned*)(q + 8);
                al[mt][3] = *(const unsigned*)(q + 8 * AS_STR + 8);
            }
#pragma unroll
            for (int nt = 0; nt < 8; nt++) {
                int n0 = (wn + nt * 8 + groupID) * AS_STR + 2 * tig;
                unsigned bh0 = *(const unsigned*)&Bs_hi[cur][n0];
                unsigned bh1 = *(const unsigned*)&Bs_hi[cur][n0 + 8];
                unsigned bl0 = *(const unsigned*)&Bs_lo[cur][n0];
                unsigned bl1 = *(const unsigned*)&Bs_lo[cur][n0 + 8];
#pragma unroll
                for (int mt = 0; mt < 2; mt++) {
                    mma16816(acc[mt][nt], ah[mt], bh0, bh1);
                    mma16816(acc[mt][nt], ah[mt], bl0, bl1);
                    mma16816(acc[mt][nt], al[mt], bh0, bh1);
                }
            }

            if (c + 1 < NC) {
                STOREBUF(cur ^ 1);
                __syncthreads();
            }
        }
#undef FETCH
#undef STOREBUF

        // ---- epilogue: bias + relu + mask + fused per-graph column pool ----
        __syncthreads();                 // all smem MMA reads done
        if (tid < 128) colsum[tid] = 0.f;
        __syncthreads();

#pragma unroll
        for (int mt = 0; mt < 2; mt++) {
            int r0 = bm + wm + mt * 16 + groupID;
            int r1 = r0 + 8;
            float km0 = keptMask ? (keptMask[r0] ? 1.f : 0.f) : 1.f;
            float km1 = keptMask ? (keptMask[r1] ? 1.f : 0.f) : 1.f;
#pragma unroll
            for (int nt = 0; nt < 8; nt++) {
                int n = wn + nt * 8 + 2 * tig;
                float b0 = bias[n], b1 = bias[n + 1];
                float2 o0, o1;
                o0.x = fmaxf(acc[mt][nt][0] + b0, 0.f) * km0;
                o0.y = fmaxf(acc[mt][nt][1] + b1, 0.f) * km0;
                o1.x = fmaxf(acc[mt][nt][2] + b0, 0.f) * km1;
                o1.y = fmaxf(acc[mt][nt][3] + b1, 0.f) * km1;
                *(float2*)(C + (size_t)r0 * HDIM + n) = o0;
                *(float2*)(C + (size_t)r1 * HDIM + n) = o1;
                atomicAdd(&colsum[n],     o0.x + o1.x);
                atomicAdd(&colsum[n + 1], o0.y + o1.y);
            }
        }
        __syncthreads();
        if (tid < 128)
            atomicAdd(&g_xs[(bm >> 9) * (4 * HDIM) + xslot * 128 + tid],
                      colsum[tid] * xinv);
        // colsum is only zeroed/read by tid<128 in program order; no extra barrier needed
    }
}

// ---------------- SAGPool scoring ----------------
__global__ void k_trel(const float* __restrict__ h, const float* __restrict__ pw_rel) {
    int node = (blockIdx.x * blockDim.x + threadIdx.x) >> 5;
    if (node >= NTOT) return;
    int lane = threadIdx.x & 31;
    float4 hv = *((const float4*)(h + (size_t)node * HDIM) + lane);
    float4 wv = *((const float4*)pw_rel + lane);
    float p = hv.x * wv.x + hv.y * wv.y + hv.z * wv.z + hv.w * wv.w;
    p = wredf(p);
    if (lane == 0) g_t[node] = p;
}

__global__ void k_score(const float* __restrict__ h, const float* __restrict__ pw_root,
                        const float* __restrict__ pb) {
    int node = (blockIdx.x * blockDim.x + threadIdx.x) >> 5;
    if (node >= NTOT) return;
    int lane = threadIdx.x & 31;
    float4 hv = *((const float4*)(h + (size_t)node * HDIM) + lane);
    float4 wv = *((const float4*)pw_root + lane);
    float p = hv.x * wv.x + hv.y * wv.y + hv.z * wv.z + hv.w * wv.w;
    int s = g_rowptr[node], e = g_rowptr[node + 1];
    for (int i = s + lane; i < e; i += 32) p += g_t[g_col[i]];
    p = wredf(p);
    if (lane == 0) g_score[node] = p + pb[0];
}

// exact top-k (k=410 of 512) per graph via rank counting; ties -> lower index
__global__ void k_topk() {
    __shared__ float s[NPG];
    int g = blockIdx.x, tid = threadIdx.x;
    float v = g_score[g * NPG + tid];
    s[tid] = v;
    __syncthreads();
    int rank = 0;
#pragma unroll 8
    for (int j = 0; j < NPG; j++) {
        float o = s[j];
        rank += (o > v) || (o == v && j < tid);
    }
    int keep = rank < KKEEP;
    g_kept[g * NPG + tid] = keep;
    g_scale[g * NPG + tid] = keep ? tanhf(v) : 0.f;
}

// ---------------- MLP head + log_softmax, block per graph ----------------
__global__ void k_mlp(const float* __restrict__ lin1W, const float* __restrict__ lin1b,
                      const float* __restrict__ lin2W, const float* __restrict__ lin2b,
                      float* __restrict__ out) {
    __shared__ float sx[512];
    __shared__ float r0[128], r1[128];
    int g = blockIdx.x, tid = threadIdx.x;
    for (int i = tid; i < 512; i += 128) sx[i] = g_xs[g * 512 + i];
    __syncthreads();
    float acc = lin1b[tid];
#pragma unroll 8
    for (int k = 0; k < 512; k++) acc += sx[k] * lin1W[k * 128 + tid];
    float hval = fmaxf(acc, 0.f);
    r0[tid] = hval * lin2W[tid * 2 + 0];
    r1[tid] = hval * lin2W[tid * 2 + 1];
    __syncthreads();
    for (int off = 64; off > 0; off >>= 1) {
        if (tid < off) { r0[tid] += r0[tid + off]; r1[tid] += r1[tid + off]; }
        __syncthreads();
    }
    if (tid == 0) {
        float z0 = r0[0] + lin2b[0], z1 = r1[0] + lin2b[1];
        float m = fmaxf(z0, z1);
        float l = m + logf(expf(z0 - m) + expf(z1 - m));
        out[g * 2 + 0] = z0 - l;
        out[g * 2 + 1] = z1 - l;
    }
}

// ---------------- launcher ----------------
extern "C" void kernel_launch(void* const* d_in, const int* in_sizes, int n_in,
                              void* d_out, int out_size) {
    const float* x       = (const float*)d_in[0];
    const int*   ei      = (const int*)  d_in[1];
    const float* W1_rel  = (const float*)d_in[3];
    const float* W1_root = (const float*)d_in[4];
    const float* b1      = (const float*)d_in[5];
    const float* Wc_rel  = (const float*)d_in[6];
    const float* Wc_root = (const float*)d_in[7];
    const float* bc      = (const float*)d_in[8];
    const float* pw_rel  = (const float*)d_in[9];
    const float* pw_root = (const float*)d_in[10];
    const float* pb      = (const float*)d_in[11];
    const float* lin1W   = (const float*)d_in[12];
    const float* lin1b   = (const float*)d_in[13];
    const float* lin2W   = (const float*)d_in[14];
    const float* lin2b   = (const float*)d_in[15];
    float* out = (float*)d_out;

    const int* srcp = ei;
    const int* dstp = ei + ETOT;

    float *hA, *hB, *agg, *scalep;
    int *degp, *kdegp, *keptp;
    cudaGetSymbolAddress((void**)&hA,     g_h);
    cudaGetSymbolAddress((void**)&hB,     g_hn);
    cudaGetSymbolAddress((void**)&agg,    g_agg);
    cudaGetSymbolAddress((void**)&degp,   g_deg);
    cudaGetSymbolAddress((void**)&kdegp,  g_kdeg);
    cudaGetSymbolAddress((void**)&keptp,  g_kept);
    cudaGetSymbolAddress((void**)&scalep, g_scale);

    // CSR build (by dst) + weight prep
    k_init   <<<NTOT / 256, 256>>>();
    k_prepw  <<<dim3(32, 1, 1), 256>>>(W1_rel, 64, 0, 1);    // slot 0
    k_prepw  <<<dim3(32, 1, 1), 256>>>(W1_root, 64, 1, 1);   // slot 1
    k_prepw  <<<dim3(64, 1, 3), 256>>>(Wc_rel, 128, 2, 2);   // slots 2,4,6
    k_prepw  <<<dim3(64, 1, 3), 256>>>(Wc_root, 128, 3, 2);  // slots 3,5,7
    k_hist   <<<ETOT / 256, 256>>>(dstp);
    k_scan1  <<<256, 256>>>();
    k_scan2  <<<1, 256>>>();
    k_scan3  <<<256, 256>>>();
    k_scatter<<<ETOT / 256, 256>>>(srcp, dstp);

    // conv1 (IN=64 -> H); mean-pool slot 0 fused into GEMM epilogue
    k_spmm64 <<<8192, 256>>>(x, agg);
    k_gemm_tc<<<GEMM_GRID, 256>>>(agg, 64, 0, x, 64, 1, nullptr, b1, nullptr,
                                  hA, 0, 1.f / (float)NPG);

    // convs[0]; pool slot 1 fused
    k_spmm128<<<8192, 256>>>(hA, agg, degp);
    k_gemm_tc<<<GEMM_GRID, 256>>>(agg, 128, 2, hA, 128, 3, nullptr, bc, nullptr,
                                  hB, 1, 1.f / (float)NPG);

    // SAGPool (score via GraphConv(H,1), aggr=add) — hB stays unscaled in memory
    k_trel <<<8192, 256>>>(hB, pw_rel);
    k_score<<<8192, 256>>>(hB, pw_root, pb);
    k_topk <<<NB, NPG>>>();

    // convs[1]: scale folded into SpMM gather + GEMM A2 staging; kdeg inline; pool slot 2 fused
    k_spmm128s<<<8192, 256>>>(hB, agg);
    k_gemm_tc <<<GEMM_GRID, 256>>>(agg, 128, 4, hB, 128, 5, scalep, bc + HDIM, keptp,
                                   hA, 2, 1.f / (float)KKEEP);

    // convs[2]; pool slot 3 fused
    k_spmm128<<<8192, 256>>>(hA, agg, kdegp);
    k_gemm_tc<<<GEMM_GRID, 256>>>(agg, 128, 6, hA, 128, 7, nullptr, bc + 2 * HDIM, keptp,
                                  hB, 3, 1.f / (float)KKEEP);

    // MLP head + log_softmax
    k_mlp<<<NB, 128>>>(lin1W, lin1b, lin2W, lin2b, out);
}

// round 15
// speedup vs baseline: 1.1579x; 1.1579x over previous
#include <cuda_runtime.h>
#include <cuda_bf16.h>
#include <math.h>

#define NTOT 65536
#define ETOT 1048576
#define INDIM 64
#define HDIM 128
#define NB 128
#define NPG 512
#define KKEEP 410   // ceil(0.8*512)

// ---------------- device scratch (no allocations allowed) ----------------
__device__ float g_h  [(size_t)NTOT * HDIM];
__device__ float g_hn [(size_t)NTOT * HDIM];
__device__ float g_agg[(size_t)NTOT * HDIM];
__device__ int   g_deg   [NTOT];
__device__ int   g_incl  [NTOT];
__device__ int   g_rowptr[NTOT + 1];
__device__ int   g_fill  [NTOT];
__device__ int   g_col   [ETOT];
__device__ int   g_bsum[256];
__device__ float g_t    [NTOT];
__device__ float g_score[NTOT];
__device__ float g_scale[NTOT];
__device__ int   g_kept [NTOT];
__device__ int   g_kdeg [NTOT];
__device__ float g_xs   [NB * 4 * HDIM];   // xcat [B][4H]

// bf16 hi/lo transposed weights: 8 slots of [N=128][K<=128]
__device__ unsigned short g_whi[8 * 128 * 128];
__device__ unsigned short g_wlo[8 * 128 * 128];

// ---------------- helpers ----------------
__device__ __forceinline__ float wredf(float v) {
    v += __shfl_xor_sync(0xFFFFFFFFu, v, 16);
    v += __shfl_xor_sync(0xFFFFFFFFu, v, 8);
    v += __shfl_xor_sync(0xFFFFFFFFu, v, 4);
    v += __shfl_xor_sync(0xFFFFFFFFu, v, 2);
    v += __shfl_xor_sync(0xFFFFFFFFu, v, 1);
    return v;
}

// ---------------- fused init + weight prep (1 launch) ----------------
// blocks 0..255   : zero g_deg + g_xs
// blocks 256..287 : W1_rel  -> slot 0 (K=64)
// blocks 288..319 : W1_root -> slot 1 (K=64)
// blocks 320..511 : Wc_rel[z]  -> slots 2,4,6 (K=128)
// blocks 512..703 : Wc_root[z] -> slots 3,5,7 (K=128)
__global__ void k_prep_all(const float* __restrict__ W1_rel,
                           const float* __restrict__ W1_root,
                           const float* __restrict__ Wc_rel,
                           const float* __restrict__ Wc_root) {
    int b = blockIdx.x, tid = threadIdx.x;
    if (b < 256) {
        int i = b * 256 + tid;
        g_deg[i] = 0;
        g_xs[i] = 0.f;
        return;
    }
    const float* W;
    int K, slot, idx;
    if (b < 288) {
        W = W1_rel;  K = 64;  slot = 0; idx = (b - 256) * 256 + tid;
    } else if (b < 320) {
        W = W1_root; K = 64;  slot = 1; idx = (b - 288) * 256 + tid;
    } else if (b < 512) {
        int t = (b - 320) * 256 + tid;
        int z = t / 16384; idx = t - z * 16384;
        W = Wc_rel + (size_t)z * 16384; K = 128; slot = 2 + 2 * z;
    } else {
        int t = (b - 512) * 256 + tid;
        int z = t / 16384; idx = t - z * 16384;
        W = Wc_root + (size_t)z * 16384; K = 128; slot = 3 + 2 * z;
    }
    if (idx >= K * 128) return;
    int n = idx / K, k = idx % K;
    float v = W[(size_t)k * 128 + n];
    __nv_bfloat16 h = __float2bfloat16_rn(v);
    __nv_bfloat16 l = __float2bfloat16_rn(v - __bfloat162float(h));
    g_whi[(size_t)slot * 16384 + idx] = __bfloat16_as_ushort(h);
    g_wlo[(size_t)slot * 16384 + idx] = __bfloat16_as_ushort(l);
}

// ---------------- CSR build ----------------
__global__ void k_hist(const int* __restrict__ dst) {
    int e = blockIdx.x * 256 + threadIdx.x;
    atomicAdd(&g_deg[dst[e]], 1);
}

__global__ void k_scan1() {
    __shared__ int s[256];
    int i = blockIdx.x * 256 + threadIdx.x;
    int v = g_deg[i];
    s[threadIdx.x] = v;
    __syncthreads();
    for (int off = 1; off < 256; off <<= 1) {
        int t = (threadIdx.x >= off) ? s[threadIdx.x - off] : 0;
        __syncthreads();
        s[threadIdx.x] += t;
        __syncthreads();
    }
    g_incl[i] = s[threadIdx.x];
    if (threadIdx.x == 255) g_bsum[blockIdx.x] = s[255];
}

// scan of block sums folded in: every block redundantly scans g_bsum (256 ints).
__global__ void k_scan3() {
    __shared__ int s[256];
    int tid = threadIdx.x;
    int myb = g_bsum[tid];
    s[tid] = myb;
    __syncthreads();
    for (int off = 1; off < 256; off <<= 1) {
        int t = (tid >= off) ? s[tid - off] : 0;
        __syncthreads();
        s[tid] += t;
        __syncthreads();
    }
    int base = s[blockIdx.x] - g_bsum[blockIdx.x];   // exclusive prefix for this block
    int i = blockIdx.x * 256 + tid;
    int incl = g_incl[i];
    int rp = base + incl - g_deg[i];
    g_rowptr[i] = rp;
    g_fill[i] = rp;
    if (i == NTOT - 1) g_rowptr[NTOT] = base + incl;
}

__global__ void k_scatter(const int* __restrict__ src, const int* __restrict__ dst) {
    int e = blockIdx.x * 256 + threadIdx.x;
    int p = atomicAdd(&g_fill[dst[e]], 1);
    g_col[p] = src[e];
}

// ---------------- SpMM (mean aggregation), warp per node ----------------
__global__ void k_spmm64(const float* __restrict__ xin, float* __restrict__ outp) {
    int node = (blockIdx.x * blockDim.x + threadIdx.x) >> 5;
    if (node >= NTOT) return;
    int lane = threadIdx.x & 31;
    int s = g_rowptr[node], e = g_rowptr[node + 1];
    float ax = 0.f, ay = 0.f;
    int i = s;
    for (; i + 3 < e; i += 4) {
        int s0 = g_col[i], s1 = g_col[i + 1], s2 = g_col[i + 2], s3 = g_col[i + 3];
        float2 v0 = *((const float2*)(xin + (size_t)s0 * INDIM) + lane);
        float2 v1 = *((const float2*)(xin + (size_t)s1 * INDIM) + lane);
        float2 v2 = *((const float2*)(xin + (size_t)s2 * INDIM) + lane);
        float2 v3 = *((const float2*)(xin + (size_t)s3 * INDIM) + lane);
        ax += v0.x + v1.x + v2.x + v3.x;
        ay += v0.y + v1.y + v2.y + v3.y;
    }
    for (; i < e; i++) {
        int s0 = g_col[i];
        float2 v0 = *((const float2*)(xin + (size_t)s0 * INDIM) + lane);
        ax += v0.x; ay += v0.y;
    }
    int c = g_deg[node];
    float inv = 1.f / (float)(c > 1 ? c : 1);
    *((float2*)(outp + (size_t)node * INDIM) + lane) = make_float2(ax * inv, ay * inv);
}

__global__ void k_spmm128(const float* __restrict__ xin, float* __restrict__ outp,
                          const int* __restrict__ cnt) {
    int node = (blockIdx.x * blockDim.x + threadIdx.x) >> 5;
    if (node >= NTOT) return;
    int lane = threadIdx.x & 31;
    int s = g_rowptr[node], e = g_rowptr[node + 1];
    float ax = 0.f, ay = 0.f, az = 0.f, aw = 0.f;
    int i = s;
    for (; i + 3 < e; i += 4) {
        int s0 = g_col[i], s1 = g_col[i + 1], s2 = g_col[i + 2], s3 = g_col[i + 3];
        float4 v0 = *((const float4*)(xin + (size_t)s0 * HDIM) + lane);
        float4 v1 = *((const float4*)(xin + (size_t)s1 * HDIM) + lane);
        float4 v2 = *((const float4*)(xin + (size_t)s2 * HDIM) + lane);
        float4 v3 = *((const float4*)(xin + (size_t)s3 * HDIM) + lane);
        ax += v0.x + v1.x + v2.x + v3.x;
        ay += v0.y + v1.y + v2.y + v3.y;
        az += v0.z + v1.z + v2.z + v3.z;
        aw += v0.w + v1.w + v2.w + v3.w;
    }
    for (; i < e; i++) {
        int s0 = g_col[i];
        float4 v0 = *((const float4*)(xin + (size_t)s0 * HDIM) + lane);
        ax += v0.x; ay += v0.y; az += v0.z; aw += v0.w;
    }
    int c = cnt[node];
    float inv = 1.f / (float)(c > 1 ? c : 1);
    *((float4*)(outp + (size_t)node * HDIM) + lane) =
        make_float4(ax * inv, ay * inv, az * inv, aw * inv);
}

// SpMM with per-source scale (SAGPool) + inline kept-degree; writes g_kdeg for conv[2].
__global__ void k_spmm128s(const float* __restrict__ xin, float* __restrict__ outp) {
    int node = (blockIdx.x * blockDim.x + threadIdx.x) >> 5;
    if (node >= NTOT) return;
    int lane = threadIdx.x & 31;
    int s = g_rowptr[node], e = g_rowptr[node + 1];
    float ax = 0.f, ay = 0.f, az = 0.f, aw = 0.f;
    int kc = 0;
    int i = s;
    for (; i + 1 < e; i += 2) {
        int s0 = g_col[i], s1 = g_col[i + 1];
        float sc0 = g_scale[s0], sc1 = g_scale[s1];
        kc += g_kept[s0] + g_kept[s1];
        float4 v0 = *((const float4*)(xin + (size_t)s0 * HDIM) + lane);
        float4 v1 = *((const float4*)(xin + (size_t)s1 * HDIM) + lane);
        ax += v0.x * sc0 + v1.x * sc1;
        ay += v0.y * sc0 + v1.y * sc1;
        az += v0.z * sc0 + v1.z * sc1;
        aw += v0.w * sc0 + v1.w * sc1;
    }
    if (i < e) {
        int s0 = g_col[i];
        float sc0 = g_scale[s0];
        kc += g_kept[s0];
        float4 v0 = *((const float4*)(xin + (size_t)s0 * HDIM) + lane);
        ax += v0.x * sc0; ay += v0.y * sc0; az += v0.z * sc0; aw += v0.w * sc0;
    }
    float inv = 1.f / (float)(kc > 1 ? kc : 1);
    *((float4*)(outp + (size_t)node * HDIM) + lane) =
        make_float4(ax * inv, ay * inv, az * inv, aw * inv);
    if (lane == 0) g_kdeg[node] = kc;
}

// ---------------- tensor-core dual GEMM (double-buffered) ----------------
// C = relu(A1@W1 + (scale2 .* A2)@W2 + b) * keptMask, bf16 hi/lo, fp32 acc.

#define AS_STR 24

__device__ __forceinline__ void mma16816(float* d, const unsigned* a, unsigned b0, unsigned b1) {
    asm volatile(
        "mma.sync.aligned.m16n8k16.row.col.f32.bf16.bf16.f32 "
        "{%0,%1,%2,%3}, {%4,%5,%6,%7}, {%8,%9}, {%0,%1,%2,%3};\n"
        : "+f"(d[0]), "+f"(d[1]), "+f"(d[2]), "+f"(d[3])
        : "r"(a[0]), "r"(a[1]), "r"(a[2]), "r"(a[3]), "r"(b0), "r"(b1));
}

__device__ __forceinline__ unsigned pack2(float x, float y, unsigned& lo) {
    __nv_bfloat16 hx = __float2bfloat16_rn(x);
    __nv_bfloat16 hy = __float2bfloat16_rn(y);
    __nv_bfloat16 lx = __float2bfloat16_rn(x - __bfloat162float(hx));
    __nv_bfloat16 ly = __float2bfloat16_rn(y - __bfloat162float(hy));
    lo = (unsigned)__bfloat16_as_ushort(lx) | ((unsigned)__bfloat16_as_ushort(ly) << 16);
    return (unsigned)__bfloat16_as_ushort(hx) | ((unsigned)__bfloat16_as_ushort(hy) << 16);
}

__global__ void __launch_bounds__(256, 2)
k_gemm_tc(const float* __restrict__ A1, int K1, int slot1,
          const float* __restrict__ A2, int K2, int slot2,
          const float* __restrict__ aScale2,
          const float* __restrict__ bias, const int* __restrict__ keptMask,
          float* __restrict__ C) {
    __shared__ __align__(16) unsigned short As_hi[2][128 * AS_STR];
    __shared__ __align__(16) unsigned short As_lo[2][128 * AS_STR];
    __shared__ __align__(16) unsigned short Bs_hi[2][128 * AS_STR];
    __shared__ __align__(16) unsigned short Bs_lo[2][128 * AS_STR];

    const int tid = threadIdx.x, wid = tid >> 5, lane = tid & 31;
    const int wm = (wid & 3) * 32;
    const int wn = (wid >> 2) * 64;
    const int groupID = lane >> 2, tig = lane & 3;
    const int bm = blockIdx.x * 128;

    const int sr = tid >> 1;
    const int sc = (tid & 1) * 8;

    const int NC1 = K1 >> 4;
    const int NC = NC1 + (K2 >> 4);

    float acc[2][8][4];
#pragma unroll
    for (int mt = 0; mt < 2; mt++)
#pragma unroll
        for (int nt = 0; nt < 8; nt++)
#pragma unroll
            for (int j = 0; j < 4; j++) acc[mt][nt][j] = 0.f;

    float4 f0, f1;
    uint4 wh, wl;
    float rowsc;

#define FETCH(cc) do {                                                         \
    int sel = ((cc) >= NC1);                                                   \
    int k0 = (sel ? (cc) - NC1 : (cc)) << 4;                                   \
    const float* A = sel ? A2 : A1;                                            \
    int K = sel ? K2 : K1;                                                     \
    const unsigned short* Wh = g_whi + (size_t)(sel ? slot2 : slot1) * 16384;  \
    const unsigned short* Wl = g_wlo + (size_t)(sel ? slot2 : slot1) * 16384;  \
    const float* ap = A + (size_t)(bm + sr) * K + k0 + sc;                     \
    f0 = *(const float4*)ap;                                                   \
    f1 = *(const float4*)(ap + 4);                                             \
    rowsc = (sel && aScale2) ? aScale2[bm + sr] : 1.f;                         \
    wh = *(const uint4*)(Wh + (size_t)sr * K + k0 + sc);                       \
    wl = *(const uint4*)(Wl + (size_t)sr * K + k0 + sc);                       \
} while (0)

#define STOREBUF(buf) do {                                                     \
    unsigned l0, l1, l2, l3;                                                   \
    unsigned h0 = pack2(f0.x * rowsc, f0.y * rowsc, l0);                       \
    unsigned h1 = pack2(f0.z * rowsc, f0.w * rowsc, l1);                       \
    unsigned h2 = pack2(f1.x * rowsc, f1.y * rowsc, l2);                       \
    unsigned h3 = pack2(f1.z * rowsc, f1.w * rowsc, l3);                       \
    *(uint4*)&As_hi[buf][sr * AS_STR + sc] = make_uint4(h0, h1, h2, h3);       \
    *(uint4*)&As_lo[buf][sr * AS_STR + sc] = make_uint4(l0, l1, l2, l3);       \
    *(uint4*)&Bs_hi[buf][sr * AS_STR + sc] = wh;                               \
    *(uint4*)&Bs_lo[buf][sr * AS_STR + sc] = wl;                               \
} while (0)

    FETCH(0);
    STOREBUF(0);
    __syncthreads();

    for (int c = 0; c < NC; c++) {
        int cur = c & 1;
        if (c + 1 < NC) FETCH(c + 1);

        unsigned ah[2][4], al[2][4];
#pragma unroll
        for (int mt = 0; mt < 2; mt++) {
            int m0 = wm + mt * 16 + groupID;
            const unsigned short* p = &As_hi[cur][m0 * AS_STR + 2 * tig];
            ah[mt][0] = *(const unsigned*)p;
            ah[mt][1] = *(const unsigned*)(p + 8 * AS_STR);
            ah[mt][2] = *(const unsigned*)(p + 8);
            ah[mt][3] = *(const unsigned*)(p + 8 * AS_STR + 8);
            const unsigned short* q = &As_lo[cur][m0 * AS_STR + 2 * tig];
            al[mt][0] = *(const unsigned*)q;
            al[mt][1] = *(const unsigned*)(q + 8 * AS_STR);
            al[mt][2] = *(const unsigned*)(q + 8);
            al[mt][3] = *(const unsigned*)(q + 8 * AS_STR + 8);
        }
#pragma unroll
        for (int nt = 0; nt < 8; nt++) {
            int n0 = (wn + nt * 8 + groupID) * AS_STR + 2 * tig;
            unsigned bh0 = *(const unsigned*)&Bs_hi[cur][n0];
            unsigned bh1 = *(const unsigned*)&Bs_hi[cur][n0 + 8];
            unsigned bl0 = *(const unsigned*)&Bs_lo[cur][n0];
            unsigned bl1 = *(const unsigned*)&Bs_lo[cur][n0 + 8];
#pragma unroll
            for (int mt = 0; mt < 2; mt++) {
                mma16816(acc[mt][nt], ah[mt], bh0, bh1);
                mma16816(acc[mt][nt], ah[mt], bl0, bl1);
                mma16816(acc[mt][nt], al[mt], bh0, bh1);
            }
        }

        if (c + 1 < NC) {
            STOREBUF(cur ^ 1);
            __syncthreads();
        }
    }
#undef FETCH
#undef STOREBUF

    // ---- epilogue: bias + relu + mask ----
#pragma unroll
    for (int mt = 0; mt < 2; mt++) {
        int r0 = bm + wm + mt * 16 + groupID;
        int r1 = r0 + 8;
        float km0 = keptMask ? (keptMask[r0] ? 1.f : 0.f) : 1.f;
        float km1 = keptMask ? (keptMask[r1] ? 1.f : 0.f) : 1.f;
#pragma unroll
        for (int nt = 0; nt < 8; nt++) {
            int n = wn + nt * 8 + 2 * tig;
            float b0 = bias[n], b1 = bias[n + 1];
            float2 o0, o1;
            o0.x = fmaxf(acc[mt][nt][0] + b0, 0.f) * km0;
            o0.y = fmaxf(acc[mt][nt][1] + b1, 0.f) * km0;
            o1.x = fmaxf(acc[mt][nt][2] + b0, 0.f) * km1;
            o1.y = fmaxf(acc[mt][nt][3] + b1, 0.f) * km1;
            *(float2*)(C + (size_t)r0 * HDIM + n) = o0;
            *(float2*)(C + (size_t)r1 * HDIM + n) = o1;
        }
    }
}

// ---------------- global mean pool into xs slot ----------------
__global__ void k_pool(const float* __restrict__ h, int slot, float inv) {
    int g = blockIdx.x, seg = blockIdx.y, c = threadIdx.x;
    const float* base = h + (size_t)(g * NPG + seg * 128) * HDIM + c;
    float acc = 0.f;
#pragma unroll 4
    for (int r = 0; r < 128; r++) acc += base[(size_t)r * HDIM];
    atomicAdd(&g_xs[g * (4 * HDIM) + slot * HDIM + c], acc * inv);
}

// ---------------- SAGPool scoring ----------------
__global__ void k_trel(const float* __restrict__ h, const float* __restrict__ pw_rel) {
    int node = (blockIdx.x * blockDim.x + threadIdx.x) >> 5;
    if (node >= NTOT) return;
    int lane = threadIdx.x & 31;
    float4 hv = *((const float4*)(h + (size_t)node * HDIM) + lane);
    float4 wv = *((const float4*)pw_rel + lane);
    float p = hv.x * wv.x + hv.y * wv.y + hv.z * wv.z + hv.w * wv.w;
    p = wredf(p);
    if (lane == 0) g_t[node] = p;
}

__global__ void k_score(const float* __restrict__ h, const float* __restrict__ pw_root,
                        const float* __restrict__ pb) {
    int node = (blockIdx.x * blockDim.x + threadIdx.x) >> 5;
    if (node >= NTOT) return;
    int lane = threadIdx.x & 31;
    float4 hv = *((const float4*)(h + (size_t)node * HDIM) + lane);
    float4 wv = *((const float4*)pw_root + lane);
    float p = hv.x * wv.x + hv.y * wv.y + hv.z * wv.z + hv.w * wv.w;
    int s = g_rowptr[node], e = g_rowptr[node + 1];
    for (int i = s + lane; i < e; i += 32) p += g_t[g_col[i]];
    p = wredf(p);
    if (lane == 0) g_score[node] = p + pb[0];
}

// exact top-k (k=410 of 512) per graph via rank counting; ties -> lower index
__global__ void k_topk() {
    __shared__ float s[NPG];
    int g = blockIdx.x, tid = threadIdx.x;
    float v = g_score[g * NPG + tid];
    s[tid] = v;
    __syncthreads();
    int rank = 0;
#pragma unroll 8
    for (int j = 0; j < NPG; j++) {
        float o = s[j];
        rank += (o > v) || (o == v && j < tid);
    }
    int keep = rank < KKEEP;
    g_kept[g * NPG + tid] = keep;
    g_scale[g * NPG + tid] = keep ? tanhf(v) : 0.f;
}

// ---------------- MLP head + log_softmax, block per graph ----------------
__global__ void k_mlp(const float* __restrict__ lin1W, const float* __restrict__ lin1b,
                      const float* __restrict__ lin2W, const float* __restrict__ lin2b,
                      float* __restrict__ out) {
    __shared__ float sx[512];
    __shared__ float r0[128], r1[128];
    int g = blockIdx.x, tid = threadIdx.x;
    for (int i = tid; i < 512; i += 128) sx[i] = g_xs[g * 512 + i];
    __syncthreads();
    float acc = lin1b[tid];
#pragma unroll 8
    for (int k = 0; k < 512; k++) acc += sx[k] * lin1W[k * 128 + tid];
    float hval = fmaxf(acc, 0.f);
    r0[tid] = hval * lin2W[tid * 2 + 0];
    r1[tid] = hval * lin2W[tid * 2 + 1];
    __syncthreads();
    for (int off = 64; off > 0; off >>= 1) {
        if (tid < off) { r0[tid] += r0[tid + off]; r1[tid] += r1[tid + off]; }
        __syncthreads();
    }
    if (tid == 0) {
        float z0 = r0[0] + lin2b[0], z1 = r1[0] + lin2b[1];
        float m = fmaxf(z0, z1);
        float l = m + logf(expf(z0 - m) + expf(z1 - m));
        out[g * 2 + 0] = z0 - l;
        out[g * 2 + 1] = z1 - l;
    }
}

// ---------------- launcher ----------------
extern "C" void kernel_launch(void* const* d_in, const int* in_sizes, int n_in,
                              void* d_out, int out_size) {
    const float* x       = (const float*)d_in[0];
    const int*   ei      = (const int*)  d_in[1];
    const float* W1_rel  = (const float*)d_in[3];
    const float* W1_root = (const float*)d_in[4];
    const float* b1      = (const float*)d_in[5];
    const float* Wc_rel  = (const float*)d_in[6];
    const float* Wc_root = (const float*)d_in[7];
    const float* bc      = (const float*)d_in[8];
    const float* pw_rel  = (const float*)d_in[9];
    const float* pw_root = (const float*)d_in[10];
    const float* pb      = (const float*)d_in[11];
    const float* lin1W   = (const float*)d_in[12];
    const float* lin1b   = (const float*)d_in[13];
    const float* lin2W   = (const float*)d_in[14];
    const float* lin2b   = (const float*)d_in[15];
    float* out = (float*)d_out;

    const int* srcp = ei;
    const int* dstp = ei + ETOT;

    float *hA, *hB, *agg, *scalep;
    int *degp, *kdegp, *keptp;
    cudaGetSymbolAddress((void**)&hA,     g_h);
    cudaGetSymbolAddress((void**)&hB,     g_hn);
    cudaGetSymbolAddress((void**)&agg,    g_agg);
    cudaGetSymbolAddress((void**)&degp,   g_deg);
    cudaGetSymbolAddress((void**)&kdegp,  g_kdeg);
    cudaGetSymbolAddress((void**)&keptp,  g_kept);
    cudaGetSymbolAddress((void**)&scalep, g_scale);

    // init + weight prep (1 launch) then CSR build
    k_prep_all<<<704, 256>>>(W1_rel, W1_root, Wc_rel, Wc_root);
    k_hist    <<<ETOT / 256, 256>>>(dstp);
    k_scan1   <<<256, 256>>>();
    k_scan3   <<<256, 256>>>();
    k_scatter <<<ETOT / 256, 256>>>(srcp, dstp);

    // conv1 (IN=64 -> H)
    k_spmm64 <<<8192, 256>>>(x, agg);
    k_gemm_tc<<<512, 256>>>(agg, 64, 0, x, 64, 1, nullptr, b1, nullptr, hA);
    k_pool   <<<dim3(NB, 4), 128>>>(hA, 0, 1.f / (float)NPG);

    // convs[0]
    k_spmm128<<<8192, 256>>>(hA, agg, degp);
    k_gemm_tc<<<512, 256>>>(agg, 128, 2, hA, 128, 3, nullptr, bc, nullptr, hB);
    k_pool   <<<dim3(NB, 4), 128>>>(hB, 1, 1.f / (float)NPG);

    // SAGPool (score via GraphConv(H,1), aggr=add) — hB stays unscaled in memory
    k_trel <<<8192, 256>>>(hB, pw_rel);
    k_score<<<8192, 256>>>(hB, pw_root, pb);
    k_topk <<<NB, NPG>>>();

    // convs[1]: scale folded into SpMM gather + GEMM A2 staging; kdeg inline
    k_spmm128s<<<8192, 256>>>(hB, agg);
    k_gemm_tc <<<512, 256>>>(agg, 128, 4, hB, 128, 5, scalep, bc + HDIM, keptp, hA);
    k_pool    <<<dim3(NB, 4), 128>>>(hA, 2, 1.f / (float)KKEEP);

    // convs[2]
    k_spmm128<<<8192, 256>>>(hA, agg, kdegp);
    k_gemm_tc<<<512, 256>>>(agg, 128, 6, hA, 128, 7, nullptr, bc + 2 * HDIM, keptp, hB);
    k_pool   <<<dim3(NB, 4), 128>>>(hB, 3, 1.f / (float)KKEEP);

    // MLP head + log_softmax
    k_mlp<<<NB, 128>>>(lin1W, lin1b, lin2W, lin2b, out);
}